// round 1
// baseline (speedup 1.0000x reference)
#include <cuda_runtime.h>
#include <stdint.h>

#define D_MODEL 2048
#define H_FF    1408
#define NE      8
#define NTOK    8192
#define SLOTS   16384
#define CAP     2048

#define BM 128
#define BN 64
#define BK 16
#define ASTR 20   // padded row stride (words) for A smem: conflict-free frag reads
#define BSTR 72   // padded row stride (words) for B smem: conflict-free frag reads

__device__ int   g_cnt[NE];
__device__ int   g_tok[SLOTS];
__device__ float g_scr[SLOTS];
__device__ float g_H[(size_t)SLOTS * H_FF];   // silu(gate)*up scratch, 92 MB

__device__ __forceinline__ uint32_t f2tf(float f) {
    uint32_t r;
    asm("cvt.rna.tf32.f32 %0, %1;" : "=r"(r) : "f"(f));
    return r;
}

__device__ __forceinline__ void mma8(float* d, const uint32_t* a, const uint32_t* b) {
    asm volatile(
        "mma.sync.aligned.m16n8k8.row.col.f32.tf32.tf32.f32 "
        "{%0,%1,%2,%3}, {%4,%5,%6,%7}, {%8,%9}, {%0,%1,%2,%3};\n"
        : "+f"(d[0]), "+f"(d[1]), "+f"(d[2]), "+f"(d[3])
        : "r"(a[0]), "r"(a[1]), "r"(a[2]), "r"(a[3]), "r"(b[0]), "r"(b[1]));
}

// ---------------------------------------------------------------------------
// Zero output + routing counters
// ---------------------------------------------------------------------------
__global__ void zero_kernel(float4* __restrict__ y, int n4) {
    int i = blockIdx.x * blockDim.x + threadIdx.x;
    if (i < n4) y[i] = make_float4(0.f, 0.f, 0.f, 0.f);
    if (blockIdx.x == 0 && threadIdx.x < NE) g_cnt[threadIdx.x] = 0;
}

// ---------------------------------------------------------------------------
// Routing: slot s -> expert bucket position (order within expert is irrelevant
// for the final segment-sum, so plain atomics suffice; no stable sort needed).
// ---------------------------------------------------------------------------
__global__ void route_kernel(const int* __restrict__ idx, const float* __restrict__ scr) {
    int s = blockIdx.x * blockDim.x + threadIdx.x;
    if (s < SLOTS) {
        int e = idx[s];
        int p = atomicAdd(&g_cnt[e], 1);
        int dst = e * CAP + p;
        g_tok[dst] = s >> 1;          // TOP_K = 2
        g_scr[dst] = scr[s];
    }
}

// ---------------------------------------------------------------------------
// GEMM1+2 fused: H[dst, :] = silu(x[tok] @ Wg[e]) * (x[tok] @ Wu[e])
// Block 128x64, 256 threads (8 warps as 4x2), warp tile 32x32,
// double-buffered smem, tf32 mma.sync m16n8k8, K streamed in BK=16 chunks.
// ---------------------------------------------------------------------------
__global__ void __launch_bounds__(256, 1) g1_kernel(
    const float* __restrict__ x,
    const float* __restrict__ Wg,
    const float* __restrict__ Wu)
{
    __shared__ uint32_t sA[2][BM][ASTR];
    __shared__ uint32_t sBg[2][BK][BSTR];
    __shared__ uint32_t sBu[2][BK][BSTR];
    __shared__ int sTok[BM];

    const int e   = blockIdx.z;
    const int bm  = blockIdx.x;
    const int bn  = blockIdx.y;
    const int tid = threadIdx.x;
    const int lane = tid & 31;
    const int warp = tid >> 5;
    const int wm = warp >> 1;   // 0..3
    const int wn = warp & 1;    // 0..1

    if (tid < BM) sTok[tid] = g_tok[e * CAP + bm * BM + tid];
    __syncthreads();

    // loader coordinates
    const int ar0 = tid >> 2;          // rows 0..63
    const int ar1 = 64 + (tid >> 2);   // rows 64..127
    const int ac  = (tid & 3) * 4;
    const int br  = tid >> 4;          // 0..15
    const int bc  = (tid & 15) * 4;    // 0..60

    const float* xr0 = x + (size_t)sTok[ar0] * D_MODEL + ac;
    const float* xr1 = x + (size_t)sTok[ar1] * D_MODEL + ac;
    const float* Bg = Wg + (size_t)e * D_MODEL * H_FF + (size_t)bn * BN + (size_t)br * H_FF + bc;
    const float* Bu = Wu + (size_t)e * D_MODEL * H_FF + (size_t)bn * BN + (size_t)br * H_FF + bc;

    float acg[8][4], acu[8][4];
    #pragma unroll
    for (int t = 0; t < 8; t++)
        #pragma unroll
        for (int q = 0; q < 4; q++) { acg[t][q] = 0.f; acu[t][q] = 0.f; }

    float4 ra0, ra1, rbg, rbu;

    // prologue: load tile 0
    ra0 = *(const float4*)(xr0);
    ra1 = *(const float4*)(xr1);
    rbg = *(const float4*)(Bg);
    rbu = *(const float4*)(Bu);
    {
        uint32_t* p0 = &sA[0][ar0][ac];
        p0[0]=f2tf(ra0.x); p0[1]=f2tf(ra0.y); p0[2]=f2tf(ra0.z); p0[3]=f2tf(ra0.w);
        uint32_t* p1 = &sA[0][ar1][ac];
        p1[0]=f2tf(ra1.x); p1[1]=f2tf(ra1.y); p1[2]=f2tf(ra1.z); p1[3]=f2tf(ra1.w);
        uint32_t* pg = &sBg[0][br][bc];
        pg[0]=f2tf(rbg.x); pg[1]=f2tf(rbg.y); pg[2]=f2tf(rbg.z); pg[3]=f2tf(rbg.w);
        uint32_t* pu = &sBu[0][br][bc];
        pu[0]=f2tf(rbu.x); pu[1]=f2tf(rbu.y); pu[2]=f2tf(rbu.z); pu[3]=f2tf(rbu.w);
    }
    __syncthreads();

    const int NT = D_MODEL / BK;   // 128
    for (int kt = 0; kt < NT; kt++) {
        const int cur = kt & 1;
        const bool more = (kt + 1 < NT);
        if (more) {
            const int k0 = (kt + 1) * BK;
            ra0 = *(const float4*)(xr0 + k0);
            ra1 = *(const float4*)(xr1 + k0);
            rbg = *(const float4*)(Bg + (size_t)k0 * H_FF);
            rbu = *(const float4*)(Bu + (size_t)k0 * H_FF);
        }
        #pragma unroll
        for (int kk = 0; kk < 2; kk++) {
            uint32_t af[2][4];
            #pragma unroll
            for (int mi = 0; mi < 2; mi++) {
                int r = wm * 32 + mi * 16 + (lane >> 2);
                int c = kk * 8 + (lane & 3);
                af[mi][0] = sA[cur][r][c];
                af[mi][1] = sA[cur][r + 8][c];
                af[mi][2] = sA[cur][r][c + 4];
                af[mi][3] = sA[cur][r + 8][c + 4];
            }
            #pragma unroll
            for (int ni = 0; ni < 4; ni++) {
                int k = kk * 8 + (lane & 3);
                int c = wn * 32 + ni * 8 + (lane >> 2);
                uint32_t bg[2] = { sBg[cur][k][c], sBg[cur][k + 4][c] };
                uint32_t bu[2] = { sBu[cur][k][c], sBu[cur][k + 4][c] };
                #pragma unroll
                for (int mi = 0; mi < 2; mi++) {
                    mma8(acg[mi * 4 + ni], af[mi], bg);
                    mma8(acu[mi * 4 + ni], af[mi], bu);
                }
            }
        }
        if (more) {
            const int nxt = cur ^ 1;
            uint32_t* p0 = &sA[nxt][ar0][ac];
            p0[0]=f2tf(ra0.x); p0[1]=f2tf(ra0.y); p0[2]=f2tf(ra0.z); p0[3]=f2tf(ra0.w);
            uint32_t* p1 = &sA[nxt][ar1][ac];
            p1[0]=f2tf(ra1.x); p1[1]=f2tf(ra1.y); p1[2]=f2tf(ra1.z); p1[3]=f2tf(ra1.w);
            uint32_t* pg = &sBg[nxt][br][bc];
            pg[0]=f2tf(rbg.x); pg[1]=f2tf(rbg.y); pg[2]=f2tf(rbg.z); pg[3]=f2tf(rbg.w);
            uint32_t* pu = &sBu[nxt][br][bc];
            pu[0]=f2tf(rbu.x); pu[1]=f2tf(rbu.y); pu[2]=f2tf(rbu.z); pu[3]=f2tf(rbu.w);
        }
        __syncthreads();
    }

    // epilogue: H = silu(gate) * up
    const size_t rowBase = (size_t)e * CAP + (size_t)bm * BM;
    const size_t colBase = (size_t)bn * BN;
    #pragma unroll
    for (int mi = 0; mi < 2; mi++)
        #pragma unroll
        for (int ni = 0; ni < 4; ni++)
            #pragma unroll
            for (int q = 0; q < 4; q++) {
                int r = wm * 32 + mi * 16 + (lane >> 2) + ((q >> 1) * 8);
                int c = wn * 32 + ni * 8 + 2 * (lane & 3) + (q & 1);
                float g = acg[mi * 4 + ni][q];
                float u = acu[mi * 4 + ni][q];
                float h = (g / (1.f + __expf(-g))) * u;
                g_H[(rowBase + r) * H_FF + colBase + c] = h;
            }
}

// ---------------------------------------------------------------------------
// GEMM3: y[tok] += score * (H[dst,:] @ Wd[e]); combine via fp32 atomicAdd
// ---------------------------------------------------------------------------
__global__ void __launch_bounds__(256, 1) g3_kernel(
    const float* __restrict__ Wd,
    float* __restrict__ y)
{
    __shared__ uint32_t sA[2][BM][ASTR];
    __shared__ uint32_t sB[2][BK][BSTR];
    __shared__ int   sTok[BM];
    __shared__ float sScr[BM];

    const int e   = blockIdx.z;
    const int bm  = blockIdx.x;
    const int bn  = blockIdx.y;
    const int tid = threadIdx.x;
    const int lane = tid & 31;
    const int warp = tid >> 5;
    const int wm = warp >> 1;
    const int wn = warp & 1;

    if (tid < BM) {
        int slot = e * CAP + bm * BM + tid;
        sTok[tid] = g_tok[slot];
        sScr[tid] = g_scr[slot];
    }
    __syncthreads();

    const int ar0 = tid >> 2;
    const int ar1 = 64 + (tid >> 2);
    const int ac  = (tid & 3) * 4;
    const int br  = tid >> 4;
    const int bc  = (tid & 15) * 4;

    const float* Ab = g_H + ((size_t)e * CAP + (size_t)bm * BM) * H_FF + ac;
    const float* Bb = Wd + (size_t)e * H_FF * D_MODEL + (size_t)bn * BN + (size_t)br * D_MODEL + bc;

    float acc[8][4];
    #pragma unroll
    for (int t = 0; t < 8; t++)
        #pragma unroll
        for (int q = 0; q < 4; q++) acc[t][q] = 0.f;

    float4 ra0, ra1, rb;
    ra0 = *(const float4*)(Ab + (size_t)ar0 * H_FF);
    ra1 = *(const float4*)(Ab + (size_t)ar1 * H_FF);
    rb  = *(const float4*)(Bb);
    {
        uint32_t* p0 = &sA[0][ar0][ac];
        p0[0]=f2tf(ra0.x); p0[1]=f2tf(ra0.y); p0[2]=f2tf(ra0.z); p0[3]=f2tf(ra0.w);
        uint32_t* p1 = &sA[0][ar1][ac];
        p1[0]=f2tf(ra1.x); p1[1]=f2tf(ra1.y); p1[2]=f2tf(ra1.z); p1[3]=f2tf(ra1.w);
        uint32_t* pb = &sB[0][br][bc];
        pb[0]=f2tf(rb.x); pb[1]=f2tf(rb.y); pb[2]=f2tf(rb.z); pb[3]=f2tf(rb.w);
    }
    __syncthreads();

    const int NT = H_FF / BK;   // 88
    for (int kt = 0; kt < NT; kt++) {
        const int cur = kt & 1;
        const bool more = (kt + 1 < NT);
        if (more) {
            const int k0 = (kt + 1) * BK;
            ra0 = *(const float4*)(Ab + (size_t)ar0 * H_FF + k0);
            ra1 = *(const float4*)(Ab + (size_t)ar1 * H_FF + k0);
            rb  = *(const float4*)(Bb + (size_t)k0 * D_MODEL);
        }
        #pragma unroll
        for (int kk = 0; kk < 2; kk++) {
            uint32_t af[2][4];
            #pragma unroll
            for (int mi = 0; mi < 2; mi++) {
                int r = wm * 32 + mi * 16 + (lane >> 2);
                int c = kk * 8 + (lane & 3);
                af[mi][0] = sA[cur][r][c];
                af[mi][1] = sA[cur][r + 8][c];
                af[mi][2] = sA[cur][r][c + 4];
                af[mi][3] = sA[cur][r + 8][c + 4];
            }
            #pragma unroll
            for (int ni = 0; ni < 4; ni++) {
                int k = kk * 8 + (lane & 3);
                int c = wn * 32 + ni * 8 + (lane >> 2);
                uint32_t bf[2] = { sB[cur][k][c], sB[cur][k + 4][c] };
                #pragma unroll
                for (int mi = 0; mi < 2; mi++)
                    mma8(acc[mi * 4 + ni], af[mi], bf);
            }
        }
        if (more) {
            const int nxt = cur ^ 1;
            uint32_t* p0 = &sA[nxt][ar0][ac];
            p0[0]=f2tf(ra0.x); p0[1]=f2tf(ra0.y); p0[2]=f2tf(ra0.z); p0[3]=f2tf(ra0.w);
            uint32_t* p1 = &sA[nxt][ar1][ac];
            p1[0]=f2tf(ra1.x); p1[1]=f2tf(ra1.y); p1[2]=f2tf(ra1.z); p1[3]=f2tf(ra1.w);
            uint32_t* pb = &sB[nxt][br][bc];
            pb[0]=f2tf(rb.x); pb[1]=f2tf(rb.y); pb[2]=f2tf(rb.z); pb[3]=f2tf(rb.w);
        }
        __syncthreads();
    }

    // epilogue: scale by score, atomic combine into y
    const size_t colBase = (size_t)bn * BN;
    #pragma unroll
    for (int mi = 0; mi < 2; mi++)
        #pragma unroll
        for (int ni = 0; ni < 4; ni++)
            #pragma unroll
            for (int q = 0; q < 4; q++) {
                int r = wm * 32 + mi * 16 + (lane >> 2) + ((q >> 1) * 8);
                int c = wn * 32 + ni * 8 + 2 * (lane & 3) + (q & 1);
                float v = acc[mi * 4 + ni][q] * sScr[r];
                atomicAdd(y + (size_t)sTok[r] * D_MODEL + colBase + c, v);
            }
}

// ---------------------------------------------------------------------------
extern "C" void kernel_launch(void* const* d_in, const int* in_sizes, int n_in,
                              void* d_out, int out_size) {
    (void)in_sizes; (void)n_in; (void)out_size;
    const float* x   = (const float*)d_in[0];
    const int*   idx = (const int*)d_in[1];
    const float* scr = (const float*)d_in[2];
    const float* Wg  = (const float*)d_in[3];
    const float* Wu  = (const float*)d_in[4];
    const float* Wd  = (const float*)d_in[5];
    float* y = (float*)d_out;

    const int n4 = NTOK * D_MODEL / 4;
    zero_kernel<<<(n4 + 255) / 256, 256>>>((float4*)y, n4);
    route_kernel<<<SLOTS / 256, 256>>>(idx, scr);
    dim3 grid1(CAP / BM, H_FF / BN, NE);     // (16, 22, 8)
    g1_kernel<<<grid1, 256>>>(x, Wg, Wu);
    dim3 grid3(CAP / BM, D_MODEL / BN, NE);  // (16, 32, 8)
    g3_kernel<<<grid3, 256>>>(Wd, y);
}

// round 3
// speedup vs baseline: 1.5730x; 1.5730x over previous
#include <cuda_runtime.h>
#include <stdint.h>

#define D_MODEL 2048
#define H_FF    1408
#define NE      8
#define NTOK    8192
#define SLOTS   16384
#define CAP     2048
#define BK      16

#define NT1     (D_MODEL / BK)   // 128
#define NT3     (H_FF / BK)      // 88

// stage layout (bytes). A: 128 rows x 20 words (pad) = 10240.
// g1 B: 16 x 72 words = 4608 each (gate, up). g3 B: 16 x 136 words = 8704.
#define A_OFF   0
#define G1_BG   10240
#define G1_BU   14848
#define G3_B    10240
#define STG     20480            // stage stride (both kernels)
#define SMEM_SZ (3 * STG)        // 61440

// ---------------- scratch ----------------
__device__ int      g_cnt[NE];
__device__ int      g_tok[SLOTS];
__device__ float    g_scr[SLOTS];
__device__ uint32_t g_xT [(size_t)NTOK * D_MODEL];        // tf32 bits
__device__ uint32_t g_WgC[(size_t)NE * D_MODEL * H_FF];   // tf32 bits, same layout
__device__ uint32_t g_WuC[(size_t)NE * D_MODEL * H_FF];
__device__ uint32_t g_WdC[(size_t)NE * H_FF * D_MODEL];
__device__ uint32_t g_H  [(size_t)NE * CAP * H_FF];       // silu(g)*u tf32 bits

// ---------------- helpers ----------------
__device__ __forceinline__ uint32_t smem_u32(const void* p) {
    uint32_t a;
    asm("{ .reg .u64 t; cvta.to.shared.u64 t, %1; cvt.u32.u64 %0, t; }" : "=r"(a) : "l"(p));
    return a;
}
__device__ __forceinline__ uint32_t f2tf(float f) {
    uint32_t r; asm("cvt.rna.tf32.f32 %0, %1;" : "=r"(r) : "f"(f)); return r;
}
__device__ __forceinline__ void cp16(uint32_t dst, const void* src) {
    asm volatile("cp.async.cg.shared.global [%0], [%1], 16;" :: "r"(dst), "l"(src));
}
__device__ __forceinline__ void cp_commit() { asm volatile("cp.async.commit_group;"); }
__device__ __forceinline__ void cp_wait1() { asm volatile("cp.async.wait_group 1;"); }
__device__ __forceinline__ void cp_wait0() { asm volatile("cp.async.wait_group 0;"); }

__device__ __forceinline__ void mma8(float* d, const uint32_t* a, const uint32_t* b) {
    asm volatile(
        "mma.sync.aligned.m16n8k8.row.col.f32.tf32.tf32.f32 "
        "{%0,%1,%2,%3}, {%4,%5,%6,%7}, {%8,%9}, {%0,%1,%2,%3};\n"
        : "+f"(d[0]), "+f"(d[1]), "+f"(d[2]), "+f"(d[3])
        : "r"(a[0]), "r"(a[1]), "r"(a[2]), "r"(a[3]), "r"(b[0]), "r"(b[1]));
}

// ---------------- pre-pass kernels ----------------
__global__ void zero_kernel(float4* __restrict__ y, int n4) {
    int i = blockIdx.x * blockDim.x + threadIdx.x;
    if (i < n4) y[i] = make_float4(0.f, 0.f, 0.f, 0.f);
    if (blockIdx.x == 0 && threadIdx.x < NE) g_cnt[threadIdx.x] = 0;
}

__global__ void route_kernel(const int* __restrict__ idx, const float* __restrict__ scr) {
    int s = blockIdx.x * blockDim.x + threadIdx.x;
    if (s < SLOTS) {
        int e = idx[s];
        int p = atomicAdd(&g_cnt[e], 1);
        g_tok[e * CAP + p] = s >> 1;     // TOP_K = 2
        g_scr[e * CAP + p] = scr[s];
    }
}

__global__ void cvt_kernel(const float4* __restrict__ src, uint4* __restrict__ dst, int n4) {
    int i = blockIdx.x * blockDim.x + threadIdx.x;
    if (i < n4) {
        float4 v = src[i];
        dst[i] = make_uint4(f2tf(v.x), f2tf(v.y), f2tf(v.z), f2tf(v.w));
    }
}

// ---------------------------------------------------------------------------
// GEMM1+2 fused. CTA: 128 slots x 64 h, gate+up. 8 warps: wm in {0,1} over
// m-halves (64 rows), wn in {0..3} over 16-wide h strips. Warp computes
// 64x16 for BOTH gate and up (A frags reused, epilogue local).
// ---------------------------------------------------------------------------
__global__ void __launch_bounds__(256, 2) g1_kernel() {
    extern __shared__ uint32_t sm[];
    const int tid = threadIdx.x, lane = tid & 31, w = tid >> 5;
    const int wm = w >> 2, wn = w & 3;
    const int ql = lane >> 2, qc = lane & 3;
    const int e = blockIdx.z, bm = blockIdx.x, bn = blockIdx.y;
    const uint32_t sbase = smem_u32(sm);

    // loader pointers
    const int arow = tid >> 1;
    const uint32_t* ap = g_xT + (size_t)g_tok[e * CAP + bm * 128 + arow] * D_MODEL + (tid & 1) * 8;
    const uint32_t ad = sbase + A_OFF + arow * 80 + (tid & 1) * 32;
    const int bkr = tid >> 4, bcw = (tid & 15) * 4;
    const uint32_t* bgp = g_WgC + ((size_t)e * D_MODEL + bkr) * H_FF + bn * 64 + bcw;
    const uint32_t* bup = g_WuC + ((size_t)e * D_MODEL + bkr) * H_FF + bn * 64 + bcw;
    const uint32_t bdg = sbase + G1_BG + bkr * 288 + bcw * 4;
    const uint32_t bdu = sbase + G1_BU + bkr * 288 + bcw * 4;

    float accg[4][2][4], accu[4][2][4];
    #pragma unroll
    for (int mi = 0; mi < 4; mi++)
        #pragma unroll
        for (int ni = 0; ni < 2; ni++)
            #pragma unroll
            for (int q = 0; q < 4; q++) { accg[mi][ni][q] = 0.f; accu[mi][ni][q] = 0.f; }

    // prologue: stages 0, 1
    #pragma unroll
    for (int s = 0; s < 2; s++) {
        uint32_t so = s * STG;
        cp16(ad + so, ap); cp16(ad + so + 16, ap + 4);
        cp16(bdg + so, bgp); cp16(bdu + so, bup);
        cp_commit();
        ap += BK; bgp += (size_t)BK * H_FF; bup += (size_t)BK * H_FF;
    }

    for (int kt = 0; kt < NT1; kt++) {
        const int s = kt % 3;
        if (kt >= NT1 - 2) cp_wait0(); else cp_wait1();
        __syncthreads();

        const uint32_t* As = sm + s * (STG / 4);
        const uint32_t* Bg = As + G1_BG / 4;
        const uint32_t* Bu = As + G1_BU / 4;
        #pragma unroll
        for (int k8 = 0; k8 < 2; k8++) {
            const int c = k8 * 8 + qc;
            uint32_t af[4][4];
            #pragma unroll
            for (int mi = 0; mi < 4; mi++) {
                const int r = wm * 64 + mi * 16 + ql;
                af[mi][0] = As[r * 20 + c];
                af[mi][1] = As[(r + 8) * 20 + c];
                af[mi][2] = As[r * 20 + c + 4];
                af[mi][3] = As[(r + 8) * 20 + c + 4];
            }
            #pragma unroll
            for (int ni = 0; ni < 2; ni++) {
                const int nn = wn * 16 + ni * 8 + ql;
                uint32_t bg[2] = { Bg[c * 72 + nn], Bg[(c + 4) * 72 + nn] };
                uint32_t bu[2] = { Bu[c * 72 + nn], Bu[(c + 4) * 72 + nn] };
                #pragma unroll
                for (int mi = 0; mi < 4; mi++) {
                    mma8(accg[mi][ni], af[mi], bg);
                    mma8(accu[mi][ni], af[mi], bu);
                }
            }
        }

        if (kt + 2 < NT1) {
            uint32_t so = ((kt + 2) % 3) * STG;
            cp16(ad + so, ap); cp16(ad + so + 16, ap + 4);
            cp16(bdg + so, bgp); cp16(bdu + so, bup);
            cp_commit();
            ap += BK; bgp += (size_t)BK * H_FF; bup += (size_t)BK * H_FF;
        }
    }

    // epilogue: h = silu(g) * u -> g_H (tf32 bits)
    const size_t rowBase = (size_t)e * CAP + (size_t)bm * 128;
    #pragma unroll
    for (int mi = 0; mi < 4; mi++)
        #pragma unroll
        for (int ni = 0; ni < 2; ni++)
            #pragma unroll
            for (int q = 0; q < 4; q++) {
                const int r = wm * 64 + mi * 16 + ql + (q >> 1) * 8;
                const int hc = wn * 16 + ni * 8 + 2 * qc + (q & 1);
                float g = accg[mi][ni][q];
                float u = accu[mi][ni][q];
                float h = (g / (1.f + __expf(-g))) * u;
                g_H[(rowBase + r) * H_FF + (size_t)bn * 64 + hc] = f2tf(h);
            }
}

// ---------------------------------------------------------------------------
// GEMM3: y[tok] += score * (H @ Wd). CTA: 128 slots x 128 d. 8 warps 2x4,
// warp 64x32.
// ---------------------------------------------------------------------------
__global__ void __launch_bounds__(256, 2) g3_kernel(float* __restrict__ y) {
    extern __shared__ uint32_t sm[];
    __shared__ int   sTok[128];
    __shared__ float sScr[128];
    const int tid = threadIdx.x, lane = tid & 31, w = tid >> 5;
    const int wm = w >> 2, wn = w & 3;
    const int ql = lane >> 2, qc = lane & 3;
    const int e = blockIdx.z, bm = blockIdx.x, bn = blockIdx.y;
    const uint32_t sbase = smem_u32(sm);

    if (tid < 128) {
        int slot = e * CAP + bm * 128 + tid;
        sTok[tid] = g_tok[slot];
        sScr[tid] = g_scr[slot];
    }

    const int arow = tid >> 1;
    const uint32_t* ap = g_H + ((size_t)e * CAP + (size_t)bm * 128 + arow) * H_FF + (tid & 1) * 8;
    const uint32_t ad = sbase + A_OFF + arow * 80 + (tid & 1) * 32;
    const int bkr = tid >> 4, bcw = (tid & 15) * 8;
    const uint32_t* bp = g_WdC + ((size_t)e * H_FF + bkr) * D_MODEL + bn * 128 + bcw;
    const uint32_t bd = sbase + G3_B + bkr * 544 + bcw * 4;

    float acc[4][4][4];
    #pragma unroll
    for (int mi = 0; mi < 4; mi++)
        #pragma unroll
        for (int ni = 0; ni < 4; ni++)
            #pragma unroll
            for (int q = 0; q < 4; q++) acc[mi][ni][q] = 0.f;

    #pragma unroll
    for (int s = 0; s < 2; s++) {
        uint32_t so = s * STG;
        cp16(ad + so, ap); cp16(ad + so + 16, ap + 4);
        cp16(bd + so, bp); cp16(bd + so + 16, bp + 4);
        cp_commit();
        ap += BK; bp += (size_t)BK * D_MODEL;
    }

    for (int kt = 0; kt < NT3; kt++) {
        const int s = kt % 3;
        if (kt >= NT3 - 2) cp_wait0(); else cp_wait1();
        __syncthreads();

        const uint32_t* As = sm + s * (STG / 4);
        const uint32_t* Bs = As + G3_B / 4;
        #pragma unroll
        for (int k8 = 0; k8 < 2; k8++) {
            const int c = k8 * 8 + qc;
            uint32_t af[4][4];
            #pragma unroll
            for (int mi = 0; mi < 4; mi++) {
                const int r = wm * 64 + mi * 16 + ql;
                af[mi][0] = As[r * 20 + c];
                af[mi][1] = As[(r + 8) * 20 + c];
                af[mi][2] = As[r * 20 + c + 4];
                af[mi][3] = As[(r + 8) * 20 + c + 4];
            }
            #pragma unroll
            for (int ni = 0; ni < 4; ni++) {
                const int nn = wn * 32 + ni * 8 + ql;
                uint32_t bf[2] = { Bs[c * 136 + nn], Bs[(c + 4) * 136 + nn] };
                #pragma unroll
                for (int mi = 0; mi < 4; mi++)
                    mma8(acc[mi][ni], af[mi], bf);
            }
        }

        if (kt + 2 < NT3) {
            uint32_t so = ((kt + 2) % 3) * STG;
            cp16(ad + so, ap); cp16(ad + so + 16, ap + 4);
            cp16(bd + so, bp); cp16(bd + so + 16, bp + 4);
            cp_commit();
            ap += BK; bp += (size_t)BK * D_MODEL;
        }
    }

    // epilogue: scale + atomic combine
    #pragma unroll
    for (int mi = 0; mi < 4; mi++) {
        #pragma unroll
        for (int q2 = 0; q2 < 2; q2++) {
            const int r = wm * 64 + mi * 16 + ql + q2 * 8;
            const float sc = sScr[r];
            float* yrow = y + (size_t)sTok[r] * D_MODEL + (size_t)bn * 128;
            #pragma unroll
            for (int ni = 0; ni < 4; ni++) {
                const int n0 = wn * 32 + ni * 8 + 2 * qc;
                atomicAdd(yrow + n0,     acc[mi][ni][q2 * 2]     * sc);
                atomicAdd(yrow + n0 + 1, acc[mi][ni][q2 * 2 + 1] * sc);
            }
        }
    }
}

// ---------------------------------------------------------------------------
extern "C" void kernel_launch(void* const* d_in, const int* in_sizes, int n_in,
                              void* d_out, int out_size) {
    (void)in_sizes; (void)n_in; (void)out_size;
    const float* x   = (const float*)d_in[0];
    const int*   idx = (const int*)d_in[1];
    const float* scr = (const float*)d_in[2];
    const float* Wg  = (const float*)d_in[3];
    const float* Wu  = (const float*)d_in[4];
    const float* Wd  = (const float*)d_in[5];
    float* y = (float*)d_out;

    const int n4x = NTOK * D_MODEL / 4;
    const int n4w = NE * D_MODEL * H_FF / 4;
    zero_kernel<<<(n4x + 255) / 256, 256>>>((float4*)y, n4x);
    route_kernel<<<SLOTS / 256, 256>>>(idx, scr);

    uint32_t* gx; cudaGetSymbolAddress((void**)&gx, g_xT);
    uint32_t* gg; cudaGetSymbolAddress((void**)&gg, g_WgC);
    uint32_t* gu; cudaGetSymbolAddress((void**)&gu, g_WuC);
    uint32_t* gd; cudaGetSymbolAddress((void**)&gd, g_WdC);
    cvt_kernel<<<(n4x + 255) / 256, 256>>>((const float4*)x, (uint4*)gx, n4x);
    cvt_kernel<<<(n4w + 255) / 256, 256>>>((const float4*)Wg, (uint4*)gg, n4w);
    cvt_kernel<<<(n4w + 255) / 256, 256>>>((const float4*)Wu, (uint4*)gu, n4w);
    cvt_kernel<<<(n4w + 255) / 256, 256>>>((const float4*)Wd, (uint4*)gd, n4w);

    cudaFuncSetAttribute(g1_kernel, cudaFuncAttributeMaxDynamicSharedMemorySize, SMEM_SZ);
    cudaFuncSetAttribute(g3_kernel, cudaFuncAttributeMaxDynamicSharedMemorySize, SMEM_SZ);

    dim3 grid1(CAP / 128, H_FF / 64, NE);     // (16, 22, 8)
    g1_kernel<<<grid1, 256, SMEM_SZ>>>();
    dim3 grid3(CAP / 128, D_MODEL / 128, NE); // (16, 16, 8)
    g3_kernel<<<grid3, 256, SMEM_SZ>>>(y);
}

// round 4
// speedup vs baseline: 2.6707x; 1.6978x over previous
#include <cuda_runtime.h>
#include <cuda_fp16.h>
#include <stdint.h>

#define D_MODEL 2048
#define H_FF    1408
#define NE      8
#define NTOK    8192
#define SLOTS   16384
#define CAP     2048
#define BK      32                 // halfs per k-tile (64B rows)

#define NT1     (D_MODEL / BK)     // 64
#define NT3     (H_FF / BK)        // 44

// smem stage layout (bytes): rows padded to 80B (20 words; conflict-free)
#define A_SZ    (128 * 80)         // 10240
#define G1_BG   10240
#define G1_BU   20480
#define G3_B    10240
#define STG     30720              // g1: A+Bg+Bu ; g3: A+B(256 rows*80=20480)
#define SMEM_SZ (3 * STG)          // 92160

// ---------------- scratch ----------------
__device__ int    g_cnt[NE];
__device__ int    g_tok[SLOTS];
__device__ float  g_scr[SLOTS];
__device__ __half g_xh [(size_t)NTOK * D_MODEL];           // fp16 row-major [tok][d]
__device__ __half g_Wgh[(size_t)NE * H_FF * D_MODEL];      // [e][h][d]  (transposed)
__device__ __half g_Wuh[(size_t)NE * H_FF * D_MODEL];      // [e][h][d]
__device__ __half g_Wdh[(size_t)NE * D_MODEL * H_FF];      // [e][d][h]  (transposed)
__device__ __half g_Hh [(size_t)SLOTS * H_FF];             // [slot][h]

// ---------------- helpers ----------------
__device__ __forceinline__ uint32_t smem_u32(const void* p) {
    uint32_t a;
    asm("{ .reg .u64 t; cvta.to.shared.u64 t, %1; cvt.u32.u64 %0, t; }" : "=r"(a) : "l"(p));
    return a;
}
__device__ __forceinline__ void cp16(uint32_t dst, const void* src) {
    asm volatile("cp.async.cg.shared.global [%0], [%1], 16;" :: "r"(dst), "l"(src));
}
__device__ __forceinline__ void cp_commit() { asm volatile("cp.async.commit_group;"); }
__device__ __forceinline__ void cp_wait1() { asm volatile("cp.async.wait_group 1;"); }
__device__ __forceinline__ void cp_wait0() { asm volatile("cp.async.wait_group 0;"); }

__device__ __forceinline__ void mma16(float* d, const uint32_t* a, const uint32_t* b) {
    asm volatile(
        "mma.sync.aligned.m16n8k16.row.col.f32.f16.f16.f32 "
        "{%0,%1,%2,%3}, {%4,%5,%6,%7}, {%8,%9}, {%0,%1,%2,%3};\n"
        : "+f"(d[0]), "+f"(d[1]), "+f"(d[2]), "+f"(d[3])
        : "r"(a[0]), "r"(a[1]), "r"(a[2]), "r"(a[3]), "r"(b[0]), "r"(b[1]));
}

// ---------------- pre-pass kernels ----------------
__global__ void zero_kernel(float4* __restrict__ y, int n4) {
    int i = blockIdx.x * blockDim.x + threadIdx.x;
    if (i < n4) y[i] = make_float4(0.f, 0.f, 0.f, 0.f);
    if (blockIdx.x == 0 && threadIdx.x < NE) g_cnt[threadIdx.x] = 0;
}

__global__ void route_kernel(const int* __restrict__ idx, const float* __restrict__ scr) {
    int s = blockIdx.x * blockDim.x + threadIdx.x;
    if (s < SLOTS) {
        int e = idx[s];
        int p = atomicAdd(&g_cnt[e], 1);
        g_tok[e * CAP + p] = s >> 1;     // TOP_K = 2
        g_scr[e * CAP + p] = scr[s];
    }
}

__global__ void cvtx_kernel(const float4* __restrict__ src, uint2* __restrict__ dst, int n4) {
    int i = blockIdx.x * blockDim.x + threadIdx.x;
    if (i < n4) {
        float4 v = src[i];
        __half2 h01 = __floats2half2_rn(v.x, v.y);
        __half2 h23 = __floats2half2_rn(v.z, v.w);
        uint2 o;
        o.x = *(uint32_t*)&h01;
        o.y = *(uint32_t*)&h23;
        dst[i] = o;
    }
}

// transpose+convert: src [e][K][N] fp32 -> dst [e][N][K] fp16. Tile 64k x 32n.
__global__ void trcvt_kernel(const float* __restrict__ src, __half* __restrict__ dst,
                             int K, int N) {
    __shared__ float t[64][33];
    const int e = blockIdx.z;
    const int k0 = blockIdx.x * 64, n0 = blockIdx.y * 32;
    const int tid = threadIdx.x;
    const float* S = src + (size_t)e * K * N;
    __half* D = dst + (size_t)e * N * K;
    #pragma unroll
    for (int it = 0; it < 2; it++) {
        int idx = tid + it * 256;
        int kr = idx >> 3, c4 = (idx & 7) * 4;
        float4 v = *(const float4*)(S + (size_t)(k0 + kr) * N + n0 + c4);
        t[kr][c4] = v.x; t[kr][c4 + 1] = v.y; t[kr][c4 + 2] = v.z; t[kr][c4 + 3] = v.w;
    }
    __syncthreads();
    #pragma unroll
    for (int it = 0; it < 4; it++) {
        int idx = tid + it * 256;
        int n = idx >> 5, k2 = idx & 31;
        __half2 h = __floats2half2_rn(t[2 * k2][n], t[2 * k2 + 1][n]);
        ((__half2*)(D + (size_t)(n0 + n) * K + k0))[k2] = h;
    }
}

// ---------------------------------------------------------------------------
// GEMM1+2 fused (fp16). CTA: 128 slots x 128 h for BOTH gate and up.
// 8 warps: wm in {0,1} (64-row halves), wn in {0..3} (32-wide h strips).
// Warp tile 64x32 per matrix. 3-stage cp.async pipeline, BK=32.
// ---------------------------------------------------------------------------
__global__ void __launch_bounds__(256, 1) g1_kernel() {
    extern __shared__ uint32_t sm[];
    const int tid = threadIdx.x, lane = tid & 31, w = tid >> 5;
    const int wm = w >> 2, wn = w & 3;
    const int ql = lane >> 2, qc = lane & 3;
    const int e = blockIdx.z, bm = blockIdx.x, bn = blockIdx.y;
    const uint32_t sbase = smem_u32(sm);

    // loader: thread covers rows r4 and r4+64, 16B chunk ck
    const int r4 = tid >> 2, ck = tid & 3;
    const __half* ap0 = g_xh + (size_t)g_tok[e * CAP + bm * 128 + r4] * D_MODEL + ck * 8;
    const __half* ap1 = g_xh + (size_t)g_tok[e * CAP + bm * 128 + r4 + 64] * D_MODEL + ck * 8;
    const size_t bbase = ((size_t)e * H_FF + (size_t)bn * 128 + r4) * D_MODEL + ck * 8;
    const __half* gp0 = g_Wgh + bbase;
    const __half* gp1 = g_Wgh + bbase + (size_t)64 * D_MODEL;
    const __half* up0 = g_Wuh + bbase;
    const __half* up1 = g_Wuh + bbase + (size_t)64 * D_MODEL;
    const uint32_t ad0 = sbase + r4 * 80 + ck * 16, ad1 = ad0 + 64 * 80;
    const uint32_t gd0 = sbase + G1_BG + r4 * 80 + ck * 16, gd1 = gd0 + 64 * 80;
    const uint32_t ud0 = sbase + G1_BU + r4 * 80 + ck * 16, ud1 = ud0 + 64 * 80;

    float accg[4][4][4], accu[4][4][4];
    #pragma unroll
    for (int mi = 0; mi < 4; mi++)
        #pragma unroll
        for (int ni = 0; ni < 4; ni++)
            #pragma unroll
            for (int q = 0; q < 4; q++) { accg[mi][ni][q] = 0.f; accu[mi][ni][q] = 0.f; }

    #pragma unroll
    for (int s = 0; s < 2; s++) {
        const uint32_t so = s * STG;
        const int ko = s * BK;
        cp16(ad0 + so, ap0 + ko); cp16(ad1 + so, ap1 + ko);
        cp16(gd0 + so, gp0 + ko); cp16(gd1 + so, gp1 + ko);
        cp16(ud0 + so, up0 + ko); cp16(ud1 + so, up1 + ko);
        cp_commit();
    }

    for (int kt = 0; kt < NT1; kt++) {
        const int s = kt % 3;
        if (kt >= NT1 - 2) cp_wait0(); else cp_wait1();
        __syncthreads();

        const uint32_t* As = sm + s * (STG / 4);
        const uint32_t* Bg = As + G1_BG / 4;
        const uint32_t* Bu = As + G1_BU / 4;
        #pragma unroll
        for (int kk = 0; kk < 2; kk++) {
            const int kb = kk * 8 + qc;
            uint32_t af[4][4];
            #pragma unroll
            for (int mi = 0; mi < 4; mi++) {
                const int r = wm * 64 + mi * 16 + ql;
                af[mi][0] = As[r * 20 + kb];
                af[mi][1] = As[(r + 8) * 20 + kb];
                af[mi][2] = As[r * 20 + kb + 4];
                af[mi][3] = As[(r + 8) * 20 + kb + 4];
            }
            #pragma unroll
            for (int ni = 0; ni < 4; ni++) {
                const int nn = wn * 32 + ni * 8 + ql;
                uint32_t bg[2] = { Bg[nn * 20 + kb], Bg[nn * 20 + kb + 4] };
                uint32_t bu[2] = { Bu[nn * 20 + kb], Bu[nn * 20 + kb + 4] };
                #pragma unroll
                for (int mi = 0; mi < 4; mi++) {
                    mma16(accg[mi][ni], af[mi], bg);
                    mma16(accu[mi][ni], af[mi], bu);
                }
            }
        }

        if (kt + 2 < NT1) {
            const uint32_t so = ((kt + 2) % 3) * STG;
            const int ko = (kt + 2) * BK;
            cp16(ad0 + so, ap0 + ko); cp16(ad1 + so, ap1 + ko);
            cp16(gd0 + so, gp0 + ko); cp16(gd1 + so, gp1 + ko);
            cp16(ud0 + so, up0 + ko); cp16(ud1 + so, up1 + ko);
            cp_commit();
        }
    }

    // epilogue: h = silu(g)*u -> fp16 H
    const size_t rowBase = (size_t)e * CAP + (size_t)bm * 128;
    const int colBase = bn * 128 + wn * 32;
    #pragma unroll
    for (int mi = 0; mi < 4; mi++)
        #pragma unroll
        for (int ni = 0; ni < 4; ni++)
            #pragma unroll
            for (int q2 = 0; q2 < 2; q2++) {
                const int r = wm * 64 + mi * 16 + ql + q2 * 8;
                float g0 = accg[mi][ni][q2 * 2],     u0 = accu[mi][ni][q2 * 2];
                float g1 = accg[mi][ni][q2 * 2 + 1], u1 = accu[mi][ni][q2 * 2 + 1];
                float h0 = (g0 / (1.f + __expf(-g0))) * u0;
                float h1 = (g1 / (1.f + __expf(-g1))) * u1;
                *(__half2*)(g_Hh + (rowBase + r) * H_FF + colBase + ni * 8 + 2 * qc) =
                    __floats2half2_rn(h0, h1);
            }
}

// ---------------------------------------------------------------------------
// GEMM3 (fp16): y[tok] += score * (H @ Wd^T). CTA: 128 slots x 256 d.
// Warp tile 64x64 (ni 0..7). K = H_FF, BK=32.
// ---------------------------------------------------------------------------
__global__ void __launch_bounds__(256, 1) g3_kernel(float* __restrict__ y) {
    extern __shared__ uint32_t sm[];
    __shared__ int   sTok[128];
    __shared__ float sScr[128];
    const int tid = threadIdx.x, lane = tid & 31, w = tid >> 5;
    const int wm = w >> 2, wn = w & 3;
    const int ql = lane >> 2, qc = lane & 3;
    const int e = blockIdx.z, bm = blockIdx.x, bn = blockIdx.y;
    const uint32_t sbase = smem_u32(sm);

    if (tid < 128) {
        int slot = e * CAP + bm * 128 + tid;
        sTok[tid] = g_tok[slot];
        sScr[tid] = g_scr[slot];
    }

    const int r4 = tid >> 2, ck = tid & 3;
    const __half* ap0 = g_Hh + ((size_t)e * CAP + (size_t)bm * 128 + r4) * H_FF + ck * 8;
    const __half* ap1 = ap0 + (size_t)64 * H_FF;
    const size_t bbase = ((size_t)e * D_MODEL + (size_t)bn * 256 + r4) * H_FF + ck * 8;
    const __half* bp0 = g_Wdh + bbase;
    const __half* bp1 = g_Wdh + bbase + (size_t)64 * H_FF;
    const __half* bp2 = g_Wdh + bbase + (size_t)128 * H_FF;
    const __half* bp3 = g_Wdh + bbase + (size_t)192 * H_FF;
    const uint32_t ad0 = sbase + r4 * 80 + ck * 16, ad1 = ad0 + 64 * 80;
    const uint32_t bd0 = sbase + G3_B + r4 * 80 + ck * 16;
    const uint32_t bd1 = bd0 + 64 * 80, bd2 = bd0 + 128 * 80, bd3 = bd0 + 192 * 80;

    float acc[4][8][4];
    #pragma unroll
    for (int mi = 0; mi < 4; mi++)
        #pragma unroll
        for (int ni = 0; ni < 8; ni++)
            #pragma unroll
            for (int q = 0; q < 4; q++) acc[mi][ni][q] = 0.f;

    #pragma unroll
    for (int s = 0; s < 2; s++) {
        const uint32_t so = s * STG;
        const int ko = s * BK;
        cp16(ad0 + so, ap0 + ko); cp16(ad1 + so, ap1 + ko);
        cp16(bd0 + so, bp0 + ko); cp16(bd1 + so, bp1 + ko);
        cp16(bd2 + so, bp2 + ko); cp16(bd3 + so, bp3 + ko);
        cp_commit();
    }

    for (int kt = 0; kt < NT3; kt++) {
        const int s = kt % 3;
        if (kt >= NT3 - 2) cp_wait0(); else cp_wait1();
        __syncthreads();

        const uint32_t* As = sm + s * (STG / 4);
        const uint32_t* Bs = As + G3_B / 4;
        #pragma unroll
        for (int kk = 0; kk < 2; kk++) {
            const int kb = kk * 8 + qc;
            uint32_t af[4][4];
            #pragma unroll
            for (int mi = 0; mi < 4; mi++) {
                const int r = wm * 64 + mi * 16 + ql;
                af[mi][0] = As[r * 20 + kb];
                af[mi][1] = As[(r + 8) * 20 + kb];
                af[mi][2] = As[r * 20 + kb + 4];
                af[mi][3] = As[(r + 8) * 20 + kb + 4];
            }
            #pragma unroll
            for (int ni = 0; ni < 8; ni++) {
                const int nn = wn * 64 + ni * 8 + ql;
                uint32_t bf[2] = { Bs[nn * 20 + kb], Bs[nn * 20 + kb + 4] };
                #pragma unroll
                for (int mi = 0; mi < 4; mi++)
                    mma16(acc[mi][ni], af[mi], bf);
            }
        }

        if (kt + 2 < NT3) {
            const uint32_t so = ((kt + 2) % 3) * STG;
            const int ko = (kt + 2) * BK;
            cp16(ad0 + so, ap0 + ko); cp16(ad1 + so, ap1 + ko);
            cp16(bd0 + so, bp0 + ko); cp16(bd1 + so, bp1 + ko);
            cp16(bd2 + so, bp2 + ko); cp16(bd3 + so, bp3 + ko);
            cp_commit();
        }
    }

    // epilogue: scale + atomic combine
    const int colBase = bn * 256 + wn * 64;
    #pragma unroll
    for (int mi = 0; mi < 4; mi++) {
        #pragma unroll
        for (int q2 = 0; q2 < 2; q2++) {
            const int r = wm * 64 + mi * 16 + ql + q2 * 8;
            const float sc = sScr[r];
            float* yrow = y + (size_t)sTok[r] * D_MODEL + colBase;
            #pragma unroll
            for (int ni = 0; ni < 8; ni++) {
                const int n0 = ni * 8 + 2 * qc;
                atomicAdd(yrow + n0,     acc[mi][ni][q2 * 2]     * sc);
                atomicAdd(yrow + n0 + 1, acc[mi][ni][q2 * 2 + 1] * sc);
            }
        }
    }
}

// ---------------------------------------------------------------------------
extern "C" void kernel_launch(void* const* d_in, const int* in_sizes, int n_in,
                              void* d_out, int out_size) {
    (void)in_sizes; (void)n_in; (void)out_size;
    const float* x   = (const float*)d_in[0];
    const int*   idx = (const int*)d_in[1];
    const float* scr = (const float*)d_in[2];
    const float* Wg  = (const float*)d_in[3];
    const float* Wu  = (const float*)d_in[4];
    const float* Wd  = (const float*)d_in[5];
    float* y = (float*)d_out;

    const int n4x = NTOK * D_MODEL / 4;
    zero_kernel<<<(n4x + 255) / 256, 256>>>((float4*)y, n4x);
    route_kernel<<<SLOTS / 256, 256>>>(idx, scr);

    __half* gx; cudaGetSymbolAddress((void**)&gx, g_xh);
    __half* gg; cudaGetSymbolAddress((void**)&gg, g_Wgh);
    __half* gu; cudaGetSymbolAddress((void**)&gu, g_Wuh);
    __half* gd; cudaGetSymbolAddress((void**)&gd, g_Wdh);

    cvtx_kernel<<<(n4x + 255) / 256, 256>>>((const float4*)x, (uint2*)gx, n4x);
    // Wg/Wu: [2048][1408] -> [1408][2048]
    dim3 tg1(D_MODEL / 64, H_FF / 32, NE);   // (32, 44, 8)
    trcvt_kernel<<<tg1, 256>>>(Wg, gg, D_MODEL, H_FF);
    trcvt_kernel<<<tg1, 256>>>(Wu, gu, D_MODEL, H_FF);
    // Wd: [1408][2048] -> [2048][1408]
    dim3 tg3(H_FF / 64, D_MODEL / 32, NE);   // (22, 64, 8)
    trcvt_kernel<<<tg3, 256>>>(Wd, gd, H_FF, D_MODEL);

    cudaFuncSetAttribute(g1_kernel, cudaFuncAttributeMaxDynamicSharedMemorySize, SMEM_SZ);
    cudaFuncSetAttribute(g3_kernel, cudaFuncAttributeMaxDynamicSharedMemorySize, SMEM_SZ);

    dim3 grid1(CAP / 128, H_FF / 128, NE);   // (16, 11, 8)
    g1_kernel<<<grid1, 256, SMEM_SZ>>>();
    dim3 grid3(CAP / 128, D_MODEL / 256, NE); // (16, 8, 8)
    g3_kernel<<<grid3, 256, SMEM_SZ>>>(y);
}